// round 15
// baseline (speedup 1.0000x reference)
#include <cuda_runtime.h>
#include <cuda_fp16.h>
#include <cstdint>

#define Bq      8
#define CIN     2
#define BINS    1024
#define FRAMES  512
#define Cc      8
#define Ee      1024
#define NTOT    (Bq * FRAMES)      // 4096 vectors per codebook channel

// ---------------- scratch (device globals: no allocation allowed) ----------
__device__ __align__(256) float  g_v [(size_t)Cc * NTOT * BINS]; // v[c][n][bin]
__device__ __align__(256) __half g_vh[(size_t)Cc * NTOT * BINS]; // fp16(v)
__device__ __align__(256) __half g_cbh[(size_t)Cc * Ee * BINS];  // fp16(cb)
__device__ __align__(256) __half g_dh[(size_t)Cc * NTOT * Ee];   // approx scores
__device__ __align__(256) float  g_e2[Cc * Ee];
__device__ __align__(256) float  g_vn2[Cc * NTOT];               // row norms^2
__device__ int   g_emax[Cc];                                     // max e2 bits
__device__ __align__(256) unsigned long long g_arg[Cc * NTOT];
__device__ float g_loss;

// ---------------- f32x2 packed helpers (Blackwell) ---------------------------
__device__ __forceinline__ uint64_t pack2(float lo, float hi) {
    uint64_t r;
    asm("mov.b64 %0, {%1, %2};" : "=l"(r) : "f"(lo), "f"(hi));
    return r;
}
__device__ __forceinline__ void unpack2(uint64_t v, float& lo, float& hi) {
    asm("mov.b64 {%0, %1}, %2;" : "=f"(lo), "=f"(hi) : "l"(v));
}
__device__ __forceinline__ void ffma2(uint64_t& d, uint64_t a, uint64_t b) {
    asm("fma.rn.f32x2 %0, %1, %2, %0;" : "+l"(d) : "l"(a), "l"(b));
}

// ---------------- init ------------------------------------------------------
__global__ void init_k() {
    int i = blockIdx.x * blockDim.x + threadIdx.x;
    if (i == 0) g_loss = 0.0f;
    if (i < Cc) g_emax[i] = 0;
}

// ---------------- fused conv1 -> leaky -> conv2 + skip -> v (+fp16) --------
// f32x2-packed: stage2 pairs output channels, stage3 pairs frame positions.
#define BT 16
#define FT 32

__global__ __launch_bounds__(256) void conv_k(
    const float* __restrict__ x,
    const float* __restrict__ w1, const float* __restrict__ b1,
    const float* __restrict__ w2, const float* __restrict__ b2,
    const float* __restrict__ ws, const float* __restrict__ bs)
{
    __shared__ float xs[CIN][BT + 16][FT + 1];
    __shared__ float h1s[Cc][BT + 8][FT + 1];
    __shared__ uint64_t w1pp[4 * CIN * 9];   // (c-pair, ci, k)
    __shared__ uint64_t w2pp[Cc * Cc * 9];   // (c, c2, k) as (w,w)
    __shared__ uint64_t wsspp[Cc * CIN];     // (c, ci) as (w,w)
    __shared__ float b1sh[Cc], b2sh[Cc], bssh[Cc];

    const int t    = threadIdx.x;
    const int bin0 = blockIdx.x * BT;
    const int f0   = blockIdx.y * FT;
    const int b    = blockIdx.z;

    // packed weights straight from global (tiny)
    for (int i = t; i < 4 * CIN * 9; i += 256) {
        int cc = i / (CIN * 9), rem = i % (CIN * 9);
        int ci = rem / 9, k = rem % 9;
        w1pp[i] = pack2(w1[((2 * cc)     * CIN + ci) * 9 + k],
                        w1[((2 * cc + 1) * CIN + ci) * 9 + k]);
    }
    for (int i = t; i < Cc * Cc * 9; i += 256) {
        float wv = w2[i];
        w2pp[i] = pack2(wv, wv);
    }
    if (t < Cc * CIN) { float wv = ws[t]; wsspp[t] = pack2(wv, wv); }
    if (t < Cc) { b1sh[t] = b1[t]; b2sh[t] = b2[t]; bssh[t] = bs[t]; }

    // load x tile with halo 8
    for (int p = t; p < CIN * (BT + 16) * FT; p += 256) {
        int f  = p % FT;
        int rb = (p / FT) % (BT + 16);
        int ci = p / (FT * (BT + 16));
        int gb = bin0 - 8 + rb;
        float v = 0.0f;
        if (gb >= 0 && gb < BINS)
            v = x[((size_t)(b * CIN + ci) * BINS + gb) * FRAMES + f0 + f];
        xs[ci][rb][f] = v;
    }
    __syncthreads();

    // stage 2: conv1 + leaky, channel-paired f32x2
    for (int p = t; p < (BT + 8) * FT; p += 256) {
        int f  = p % FT;
        int rb = p / FT;
        int gb = bin0 - 4 + rb;
        uint64_t acc2[4];
#pragma unroll
        for (int cc = 0; cc < 4; cc++)
            acc2[cc] = pack2(b1sh[2 * cc], b1sh[2 * cc + 1]);
#pragma unroll
        for (int ci = 0; ci < CIN; ci++)
#pragma unroll
            for (int k = 0; k < 9; k++) {
                float xv = xs[ci][rb + k][f];
                uint64_t xv2 = pack2(xv, xv);
#pragma unroll
                for (int cc = 0; cc < 4; cc++)
                    ffma2(acc2[cc], xv2, w1pp[(cc * CIN + ci) * 9 + k]);
            }
#pragma unroll
        for (int cc = 0; cc < 4; cc++) {
            float h0, h1v;
            unpack2(acc2[cc], h0, h1v);
            h0  = (h0  >= 0.0f) ? h0  : 0.2f * h0;
            h1v = (h1v >= 0.0f) ? h1v : 0.2f * h1v;
            if (gb < 0 || gb >= BINS) { h0 = 0.0f; h1v = 0.0f; }
            h1s[2 * cc][rb][f]     = h0;
            h1s[2 * cc + 1][rb][f] = h1v;
        }
    }
    __syncthreads();

    // stage 3: conv2 + skip, position-paired f32x2
    const int binL = t % BT;
    const int fL0  = t / BT;
    uint64_t acc2[Cc];
#pragma unroll
    for (int c = 0; c < Cc; c++) {
        float bb = b2sh[c] + bssh[c];
        acc2[c] = pack2(bb, bb);
    }
#pragma unroll
    for (int c2 = 0; c2 < Cc; c2++)
#pragma unroll
        for (int k = 0; k < 9; k++) {
            uint64_t hv2 = pack2(h1s[c2][binL + k][fL0],
                                 h1s[c2][binL + k][fL0 + 16]);
#pragma unroll
            for (int c = 0; c < Cc; c++)
                ffma2(acc2[c], hv2, w2pp[(c * Cc + c2) * 9 + k]);
        }
#pragma unroll
    for (int ci = 0; ci < CIN; ci++) {
        uint64_t xv2 = pack2(xs[ci][binL + 8][fL0],
                             xs[ci][binL + 8][fL0 + 16]);
#pragma unroll
        for (int c = 0; c < Cc; c++)
            ffma2(acc2[c], xv2, wsspp[c * CIN + ci]);
    }

    const int gb = bin0 + binL;
    const int n0 = b * FRAMES + f0 + fL0;
#pragma unroll
    for (int c = 0; c < Cc; c++) {
        float v0, v1;
        unpack2(acc2[c], v0, v1);
        size_t idx0 = ((size_t)c * NTOT + n0) * BINS + gb;
        size_t idx1 = ((size_t)c * NTOT + n0 + 16) * BINS + gb;
        g_v[idx0]  = v0;  g_vh[idx0] = __float2half(v0);
        g_v[idx1]  = v1;  g_vh[idx1] = __float2half(v1);
    }
}

// ---------------- e2 + fp16(cb) + per-channel max e2 ------------------------
__global__ void e2_k(const float* __restrict__ cb) {
    int warp = threadIdx.x >> 5, lane = threadIdx.x & 31;
    int row  = blockIdx.x * 8 + warp;              // 0..8191
    const size_t base = (size_t)row * BINS;
    float s = 0.0f;
    for (int j = lane; j < BINS; j += 32) {
        float v = cb[base + j];
        s += v * v;
        g_cbh[base + j] = __float2half(v);
    }
#pragma unroll
    for (int o = 16; o; o >>= 1) s += __shfl_down_sync(0xffffffffu, s, o);
    if (lane == 0) {
        g_e2[row] = s;
        atomicMax(&g_emax[row / Ee], __float_as_int(s));   // s >= 0
    }
}

// ---------------- vn2 = ||v row||^2 -----------------------------------------
__global__ void vn2_k() {
    int warp = threadIdx.x >> 5, lane = threadIdx.x & 31;
    int row  = blockIdx.x * 8 + warp;              // 0..32767
    const float4* p = (const float4*)(g_v + (size_t)row * BINS);
    float s = 0.0f;
#pragma unroll
    for (int j = 0; j < 8; j++) {
        float4 v = p[lane + 32 * j];
        s += v.x * v.x + v.y * v.y + v.z * v.z + v.w * v.w;
    }
#pragma unroll
    for (int o = 16; o; o >>= 1) s += __shfl_down_sync(0xffffffffu, s, o);
    if (lane == 0) g_vn2[row] = s;
}

// ---------------- 1-pass fp16 tensor GEMM -> approx scores (fp16) -----------
#define BM   128
#define BE   128
#define BKh  64
#define MATB 16384
#define BUFB (2 * MATB)
#define GEMM_SMEM_BYTES (2 * BUFB)    // 65536

__device__ __forceinline__ void cp16(uint32_t dst, const void* src) {
    asm volatile("cp.async.cg.shared.global [%0], [%1], 16;" :: "r"(dst), "l"(src));
}

__device__ __forceinline__ void ldsm_x4(uint32_t a, uint32_t& r0, uint32_t& r1,
                                        uint32_t& r2, uint32_t& r3) {
    asm volatile("ldmatrix.sync.aligned.m8n8.x4.shared.b16 {%0,%1,%2,%3}, [%4];"
                 : "=r"(r0), "=r"(r1), "=r"(r2), "=r"(r3) : "r"(a));
}
__device__ __forceinline__ void ldsm_x2(uint32_t a, uint32_t& r0, uint32_t& r1) {
    asm volatile("ldmatrix.sync.aligned.m8n8.x2.shared.b16 {%0,%1}, [%2];"
                 : "=r"(r0), "=r"(r1) : "r"(a));
}

#define MMA_F16(d, a, b) \
    asm volatile("mma.sync.aligned.m16n8k16.row.col.f32.f16.f16.f32 " \
                 "{%0,%1,%2,%3}, {%4,%5,%6,%7}, {%8,%9}, {%0,%1,%2,%3};" \
                 : "+f"(d[0]), "+f"(d[1]), "+f"(d[2]), "+f"(d[3]) \
                 : "r"(a[0]), "r"(a[1]), "r"(a[2]), "r"(a[3]), \
                   "r"(b[0]), "r"(b[1]))

__global__ __launch_bounds__(256, 2) void gemm_k() {
    extern __shared__ __align__(128) char S[];
    __shared__ float e2s[BE];

    const int t    = threadIdx.x;
    const int lane = t & 31;
    const int w    = t >> 5;
    const int m_base = (w >> 2) * 64;
    const int n_base = (w & 3) * 32;

    const int c     = blockIdx.z;
    const int eBase = blockIdx.x * BE;
    const int mBase = blockIdx.y * BM;

    const __half* srcA = g_vh  + (size_t)c * NTOT * BINS + (size_t)mBase * BINS;
    const __half* srcB = g_cbh + (size_t)c * Ee   * BINS + (size_t)eBase * BINS;

    const uint32_t sbase = (uint32_t)__cvta_generic_to_shared(S);

    auto load_slab = [&](int k0, int buf) {
#pragma unroll
        for (int i = 0; i < 8; i++) {
            int id  = t + 256 * i;
            int m   = id >> 10;
            int cid = id & 1023;
            int row = cid >> 3;
            int q   = cid & 7;
            const __half* src = (m == 0 ? srcA : srcB) + (size_t)row * BINS + k0 + q * 8;
            cp16(sbase + (uint32_t)(buf * BUFB + m * MATB + row * 128
                                    + ((q ^ (row & 7)) << 4)),
                 src);
        }
        asm volatile("cp.async.commit_group;");
    };

    float acc[4][4][4];
#pragma unroll
    for (int mi = 0; mi < 4; mi++)
#pragma unroll
        for (int ni = 0; ni < 4; ni++)
#pragma unroll
            for (int r = 0; r < 4; r++) acc[mi][ni][r] = 0.0f;

    load_slab(0, 0);
    if (t < BE) e2s[t] = g_e2[c * Ee + eBase + t];

    const int amat = lane >> 3;
    const int arow = lane & 7;
    const int a_row_off = ((amat & 1) << 3) + arow;
    const int a_ck_off  = amat >> 1;
    const int b_ck_off  = amat & 1;

    for (int s = 0; s < BINS / BKh; s++) {
        const int buf = s & 1;
        asm volatile("cp.async.wait_group 0;");
        __syncthreads();
        if (s + 1 < BINS / BKh) load_slab((s + 1) * BKh, buf ^ 1);

        const uint32_t Ah = sbase + buf * BUFB;
        const uint32_t Bh = Ah + MATB;

#pragma unroll
        for (int ks = 0; ks < BKh; ks += 16) {
            const int cks = ks >> 3;
            uint32_t aF[4][4], bF[4][2];
#pragma unroll
            for (int mi = 0; mi < 4; mi++) {
                int row = m_base + mi * 16 + a_row_off;
                int ch  = cks + a_ck_off;
                ldsm_x4(Ah + row * 128 + ((ch ^ (row & 7)) << 4),
                        aF[mi][0], aF[mi][1], aF[mi][2], aF[mi][3]);
            }
#pragma unroll
            for (int ni = 0; ni < 4; ni++) {
                int row = n_base + ni * 8 + arow;
                int ch  = cks + b_ck_off;
                ldsm_x2(Bh + row * 128 + ((ch ^ (row & 7)) << 4),
                        bF[ni][0], bF[ni][1]);
            }
#pragma unroll
            for (int mi = 0; mi < 4; mi++)
#pragma unroll
                for (int ni = 0; ni < 4; ni++)
                    MMA_F16(acc[mi][ni], aF[mi], bF[ni]);
        }
        __syncthreads();
    }

    // epilogue: write approx scores e2 - 2*dot as fp16 (half2 stores)
    const int r4 = lane >> 2;
    const int c4 = lane & 3;
#pragma unroll
    for (int mi = 0; mi < 4; mi++)
#pragma unroll
        for (int h = 0; h < 2; h++) {
            int grow = mBase + m_base + mi * 16 + r4 + h * 8;
            __half* dr = g_dh + ((size_t)c * NTOT + grow) * Ee + eBase;
#pragma unroll
            for (int ni = 0; ni < 4; ni++) {
                int cl = n_base + ni * 8 + c4 * 2;
                float sx = e2s[cl]     - 2.0f * acc[mi][ni][h * 2 + 0];
                float sy = e2s[cl + 1] - 2.0f * acc[mi][ni][h * 2 + 1];
                *(__half2*)(dr + cl) = __floats2half2_rn(sx, sy);
            }
        }
}

// ---------------- select: certified argmin, warp per row --------------------
#define CAND_CAP 128

__global__ __launch_bounds__(256) void select_k(const float* __restrict__ cb) {
    __shared__ int scand[8][CAND_CAP];
    __shared__ int scnt[8];

    const int t    = threadIdx.x;
    const int lane = t & 31;
    const int wp   = t >> 5;
    const int n    = blockIdx.x * 8 + wp;
    const int c    = blockIdx.y;
    const size_t row = (size_t)c * NTOT + n;

    const uint4* dr = (const uint4*)(g_dh + row * Ee);
    uint4 sc[4];
    float lmin = 3.4e38f;
#pragma unroll
    for (int j = 0; j < 4; j++) {
        sc[j] = dr[lane + 32 * j];
        const __half2* h2 = (const __half2*)&sc[j];
#pragma unroll
        for (int k = 0; k < 4; k++) {
            float2 f2 = __half22float2(h2[k]);
            lmin = fminf(lmin, fminf(f2.x, f2.y));
        }
    }
#pragma unroll
    for (int o = 16; o; o >>= 1)
        lmin = fminf(lmin, __shfl_xor_sync(0xffffffffu, lmin, o));

    const float sv = sqrtf(g_vn2[row]);
    const float se = sqrtf(__int_as_float(g_emax[c]));
    const float M  = (sv + se) * (sv + se);        // bound on |score|
    const float thr = lmin + 2.0f * (0.002f * sv * se + 0.1f) + 0.001f * M;

    int cntL = 0, idxL = 0x7fffffff;
#pragma unroll
    for (int j = 0; j < 4; j++) {
        const __half2* h2 = (const __half2*)&sc[j];
        int base = 8 * (lane + 32 * j);
#pragma unroll
        for (int k = 0; k < 4; k++) {
            float2 f2 = __half22float2(h2[k]);
            if (f2.x <= thr) { cntL++; idxL = min(idxL, base + 2 * k); }
            if (f2.y <= thr) { cntL++; idxL = min(idxL, base + 2 * k + 1); }
        }
    }
    int cnt = cntL, idxm = idxL;
#pragma unroll
    for (int o = 16; o; o >>= 1) {
        cnt  += __shfl_xor_sync(0xffffffffu, cnt, o);
        idxm  = min(idxm, __shfl_xor_sync(0xffffffffu, idxm, o));
    }

    if (cnt == 1) {            // sole candidate in certified window = argmin
        if (lane == 0) g_arg[row] = (unsigned long long)(unsigned)idxm;
        return;
    }

    if (lane == 0) scnt[wp] = 0;
    __syncwarp();
    bool full_scan = (cnt > CAND_CAP);
    if (!full_scan) {
#pragma unroll
        for (int j = 0; j < 4; j++) {
            const __half2* h2 = (const __half2*)&sc[j];
            int base = 8 * (lane + 32 * j);
#pragma unroll
            for (int k = 0; k < 4; k++) {
                float2 f2 = __half22float2(h2[k]);
                if (f2.x <= thr) scand[wp][atomicAdd(&scnt[wp], 1)] = base + 2 * k;
                if (f2.y <= thr) scand[wp][atomicAdd(&scnt[wp], 1)] = base + 2 * k + 1;
            }
        }
    }
    __syncwarp();

    const float4* vr = (const float4*)(g_v + row * BINS);
    float4 v[8];
#pragma unroll
    for (int j = 0; j < 8; j++) v[j] = vr[lane + 32 * j];

    float best = 3.4e38f;
    int   bidx = 0x7fffffff;
    const int total = full_scan ? Ee : cnt;
    for (int ci = 0; ci < total; ci++) {
        const int e = full_scan ? ci : scand[wp][ci];
        const float4* cr = (const float4*)(cb + ((size_t)c * Ee + e) * BINS);
        float p = 0.0f;
#pragma unroll
        for (int j = 0; j < 8; j++) {
            float4 cv = cr[lane + 32 * j];
            p += v[j].x * cv.x + v[j].y * cv.y + v[j].z * cv.z + v[j].w * cv.w;
        }
#pragma unroll
        for (int o = 16; o; o >>= 1)
            p += __shfl_xor_sync(0xffffffffu, p, o);
        float s = g_e2[c * Ee + e] - 2.0f * p;
        if (s < best || (s == best && e < bidx)) { best = s; bidx = e; }
    }
    if (lane == 0) g_arg[row] = (unsigned long long)(unsigned)bidx;
}

// ---------------- gather + transpose + channel-reverse + loss --------------
__global__ __launch_bounds__(256) void gather_k(const float* __restrict__ cb,
                                                float* __restrict__ out)
{
    __shared__ float qs[32][33];
    __shared__ int   idxs[32];
    __shared__ float rsum[256];

    const int t    = threadIdx.x;
    const int c    = blockIdx.z;
    const int n0   = blockIdx.y * 32;
    const int bin0 = blockIdx.x * 32;

    if (t < 32) idxs[t] = (int)(g_arg[c * NTOT + n0 + t] & 0xFFFFFFFFULL);
    __syncthreads();

    {
        int binL = t % 32, fL0 = t / 32;
        float lacc = 0.0f;
#pragma unroll
        for (int i = 0; i < 4; i++) {
            int fL = fL0 + 8 * i;
            int n  = n0 + fL;
            float qv = cb[((size_t)c * Ee + idxs[fL]) * BINS + bin0 + binL];
            float vv = g_v[((size_t)c * NTOT + n) * BINS + bin0 + binL];
            float d = qv - vv;
            lacc += d * d;
            qs[fL][binL] = qv;
        }
        rsum[t] = lacc;
    }
    __syncthreads();

    {
        int fL = t % 32, bL0 = t / 32;
        int b = n0 / FRAMES, fbase = n0 % FRAMES;
        int cOut = (Cc - 1) - c;
#pragma unroll
        for (int i = 0; i < 4; i++) {
            int bL = bL0 + 8 * i;
            out[(((size_t)b * Cc + cOut) * BINS + bin0 + bL) * FRAMES + fbase + fL]
                = qs[fL][bL];
        }
    }
    __syncthreads();
    for (int s2 = 128; s2; s2 >>= 1) {
        if (t < s2) rsum[t] += rsum[t + s2];
        __syncthreads();
    }
    if (t == 0) atomicAdd(&g_loss, rsum[0]);
}

// ---------------- finalize loss --------------------------------------------
__global__ void fin_k(float* __restrict__ out, int lossIdx) {
    if (threadIdx.x == 0)
        out[lossIdx] = 1.25f * g_loss / (float)((size_t)NTOT * BINS);
}

// ---------------- launch ----------------------------------------------------
extern "C" void kernel_launch(void* const* d_in, const int* in_sizes, int n_in,
                              void* d_out, int out_size)
{
    const float* x  = (const float*)d_in[0];
    const float* w1 = (const float*)d_in[1];
    const float* b1 = (const float*)d_in[2];
    const float* w2 = (const float*)d_in[3];
    const float* b2 = (const float*)d_in[4];
    const float* ws = (const float*)d_in[5];
    const float* bs = (const float*)d_in[6];
    const float* cb = (const float*)d_in[7];
    float* out = (float*)d_out;

    cudaFuncSetAttribute(gemm_k,
                         cudaFuncAttributeMaxDynamicSharedMemorySize,
                         GEMM_SMEM_BYTES);

    init_k<<<1, 256>>>();
    conv_k<<<dim3(BINS / BT, FRAMES / FT, Bq), 256>>>(x, w1, b1, w2, b2, ws, bs);
    e2_k<<<(Cc * Ee) / 8, 256>>>(cb);
    vn2_k<<<(Cc * NTOT) / 8, 256>>>();
    gemm_k<<<dim3(Ee / BE, NTOT / BM, Cc), 256, GEMM_SMEM_BYTES>>>();
    select_k<<<dim3(NTOT / 8, Cc), 256>>>(cb);
    gather_k<<<dim3(BINS / 32, NTOT / 32, Cc), 256>>>(cb, out);
    fin_k<<<1, 32>>>(out, out_size - 1);
}

// round 16
// speedup vs baseline: 1.1020x; 1.1020x over previous
#include <cuda_runtime.h>
#include <cuda_fp16.h>
#include <cstdint>

#define Bq      8
#define CIN     2
#define BINS    1024
#define FRAMES  512
#define Cc      8
#define Ee      1024
#define NTOT    (Bq * FRAMES)      // 4096 vectors per codebook channel

// ---------------- scratch (device globals: no allocation allowed) ----------
__device__ __align__(256) float  g_v [(size_t)Cc * NTOT * BINS]; // v[c][n][bin]
__device__ __align__(256) __half g_vh[(size_t)Cc * NTOT * BINS]; // fp16(v)
__device__ __align__(256) __half g_cbh[(size_t)Cc * Ee * BINS];  // fp16(cb)
__device__ __align__(256) __half g_dh[(size_t)Cc * NTOT * Ee];   // approx scores
__device__ __align__(256) float  g_e2[Cc * Ee];
__device__ __align__(256) float  g_vn2[Cc * NTOT];               // row norms^2
__device__ int   g_emax[Cc];                                     // max e2 bits
__device__ __align__(256) unsigned long long g_arg[Cc * NTOT];
__device__ float g_loss;

// ---------------- init ------------------------------------------------------
__global__ void init_k() {
    int i = blockIdx.x * blockDim.x + threadIdx.x;
    if (i == 0) g_loss = 0.0f;
    if (i < Cc) g_emax[i] = 0;
}

// ---------------- fused conv1 -> leaky -> conv2 + skip -> v (+fp16) --------
#define BT 16
#define FT 32

__global__ __launch_bounds__(256) void conv_k(
    const float* __restrict__ x,
    const float* __restrict__ w1, const float* __restrict__ b1,
    const float* __restrict__ w2, const float* __restrict__ b2,
    const float* __restrict__ ws, const float* __restrict__ bs)
{
    __shared__ float xs[CIN][BT + 16][FT + 1];
    __shared__ float h1s[Cc][BT + 8][FT + 1];
    __shared__ float w1s[Cc * CIN * 9];
    __shared__ float w2s[Cc * Cc * 9];
    __shared__ float wss[Cc * CIN];
    __shared__ float b1sh[Cc], b2sh[Cc], bssh[Cc];

    const int t    = threadIdx.x;
    const int bin0 = blockIdx.x * BT;
    const int f0   = blockIdx.y * FT;
    const int b    = blockIdx.z;

    for (int i = t; i < Cc * CIN * 9; i += 256) w1s[i] = w1[i];
    for (int i = t; i < Cc * Cc * 9;  i += 256) w2s[i] = w2[i];
    if (t < Cc * CIN) wss[t] = ws[t];
    if (t < Cc) { b1sh[t] = b1[t]; b2sh[t] = b2[t]; bssh[t] = bs[t]; }

    for (int p = t; p < CIN * (BT + 16) * FT; p += 256) {
        int f  = p % FT;
        int rb = (p / FT) % (BT + 16);
        int ci = p / (FT * (BT + 16));
        int gb = bin0 - 8 + rb;
        float v = 0.0f;
        if (gb >= 0 && gb < BINS)
            v = x[((size_t)(b * CIN + ci) * BINS + gb) * FRAMES + f0 + f];
        xs[ci][rb][f] = v;
    }
    __syncthreads();

    for (int p = t; p < (BT + 8) * FT; p += 256) {
        int f  = p % FT;
        int rb = p / FT;
        int gb = bin0 - 4 + rb;
        float acc[Cc];
#pragma unroll
        for (int c = 0; c < Cc; c++) acc[c] = b1sh[c];
#pragma unroll
        for (int ci = 0; ci < CIN; ci++)
#pragma unroll
            for (int k = 0; k < 9; k++) {
                float xv = xs[ci][rb + k][f];
#pragma unroll
                for (int c = 0; c < Cc; c++)
                    acc[c] += xv * w1s[(c * CIN + ci) * 9 + k];
            }
#pragma unroll
        for (int c = 0; c < Cc; c++) {
            float h = acc[c];
            h = (h >= 0.0f) ? h : 0.2f * h;
            if (gb < 0 || gb >= BINS) h = 0.0f;
            h1s[c][rb][f] = h;
        }
    }
    __syncthreads();

    const int binL = t % BT;
    const int fL0  = t / BT;
    float acc[2][Cc];
#pragma unroll
    for (int i = 0; i < 2; i++)
#pragma unroll
        for (int c = 0; c < Cc; c++) acc[i][c] = b2sh[c] + bssh[c];

#pragma unroll
    for (int c2 = 0; c2 < Cc; c2++)
#pragma unroll
        for (int k = 0; k < 9; k++) {
            float w[Cc];
#pragma unroll
            for (int c = 0; c < Cc; c++) w[c] = w2s[(c * Cc + c2) * 9 + k];
#pragma unroll
            for (int i = 0; i < 2; i++) {
                float hv = h1s[c2][binL + k][fL0 + 16 * i];
#pragma unroll
                for (int c = 0; c < Cc; c++) acc[i][c] += hv * w[c];
            }
        }
#pragma unroll
    for (int ci = 0; ci < CIN; ci++)
#pragma unroll
        for (int i = 0; i < 2; i++) {
            float xv = xs[ci][binL + 8][fL0 + 16 * i];
#pragma unroll
            for (int c = 0; c < Cc; c++) acc[i][c] += xv * wss[c * CIN + ci];
        }

    const int gb = bin0 + binL;
#pragma unroll
    for (int i = 0; i < 2; i++) {
        int n = b * FRAMES + f0 + fL0 + 16 * i;
#pragma unroll
        for (int c = 0; c < Cc; c++) {
            size_t idx = ((size_t)c * NTOT + n) * BINS + gb;
            float vv = acc[i][c];
            g_v[idx]  = vv;
            g_vh[idx] = __float2half(vv);
        }
    }
}

// ---------------- e2 + fp16(cb) + per-channel max e2 ------------------------
__global__ void e2_k(const float* __restrict__ cb) {
    int warp = threadIdx.x >> 5, lane = threadIdx.x & 31;
    int row  = blockIdx.x * 8 + warp;              // 0..8191
    const size_t base = (size_t)row * BINS;
    float s = 0.0f;
    for (int j = lane; j < BINS; j += 32) {
        float v = cb[base + j];
        s += v * v;
        g_cbh[base + j] = __float2half(v);
    }
#pragma unroll
    for (int o = 16; o; o >>= 1) s += __shfl_down_sync(0xffffffffu, s, o);
    if (lane == 0) {
        g_e2[row] = s;
        atomicMax(&g_emax[row / Ee], __float_as_int(s));   // s >= 0
    }
}

// ---------------- vn2 ~= ||v row||^2 from fp16 (threshold-only) -------------
__global__ void vn2_k() {
    int warp = threadIdx.x >> 5, lane = threadIdx.x & 31;
    int row  = blockIdx.x * 8 + warp;              // 0..32767
    const uint4* p = (const uint4*)(g_vh + (size_t)row * BINS);
    float s = 0.0f;
#pragma unroll
    for (int j = 0; j < 4; j++) {
        uint4 u = p[lane + 32 * j];
        const __half2* h2 = (const __half2*)&u;
#pragma unroll
        for (int k = 0; k < 4; k++) {
            float2 f2 = __half22float2(h2[k]);
            s += f2.x * f2.x + f2.y * f2.y;
        }
    }
#pragma unroll
    for (int o = 16; o; o >>= 1) s += __shfl_down_sync(0xffffffffu, s, o);
    if (lane == 0) g_vn2[row] = s;
}

// ---------------- 1-pass fp16 tensor GEMM -> approx scores (fp16) -----------
#define BM   128
#define BE   128
#define BKh  64
#define MATB 16384
#define BUFB (2 * MATB)
#define GEMM_SMEM_BYTES (2 * BUFB)    // 65536

__device__ __forceinline__ void cp16(uint32_t dst, const void* src) {
    asm volatile("cp.async.cg.shared.global [%0], [%1], 16;" :: "r"(dst), "l"(src));
}

__device__ __forceinline__ void ldsm_x4(uint32_t a, uint32_t& r0, uint32_t& r1,
                                        uint32_t& r2, uint32_t& r3) {
    asm volatile("ldmatrix.sync.aligned.m8n8.x4.shared.b16 {%0,%1,%2,%3}, [%4];"
                 : "=r"(r0), "=r"(r1), "=r"(r2), "=r"(r3) : "r"(a));
}
__device__ __forceinline__ void ldsm_x2(uint32_t a, uint32_t& r0, uint32_t& r1) {
    asm volatile("ldmatrix.sync.aligned.m8n8.x2.shared.b16 {%0,%1}, [%2];"
                 : "=r"(r0), "=r"(r1) : "r"(a));
}

#define MMA_F16(d, a, b) \
    asm volatile("mma.sync.aligned.m16n8k16.row.col.f32.f16.f16.f32 " \
                 "{%0,%1,%2,%3}, {%4,%5,%6,%7}, {%8,%9}, {%0,%1,%2,%3};" \
                 : "+f"(d[0]), "+f"(d[1]), "+f"(d[2]), "+f"(d[3]) \
                 : "r"(a[0]), "r"(a[1]), "r"(a[2]), "r"(a[3]), \
                   "r"(b[0]), "r"(b[1]))

__global__ __launch_bounds__(256, 2) void gemm_k() {
    extern __shared__ __align__(128) char S[];
    __shared__ float e2s[BE];

    const int t    = threadIdx.x;
    const int lane = t & 31;
    const int w    = t >> 5;
    const int m_base = (w >> 2) * 64;
    const int n_base = (w & 3) * 32;

    const int c     = blockIdx.z;
    const int eBase = blockIdx.x * BE;
    const int mBase = blockIdx.y * BM;

    const __half* srcA = g_vh  + (size_t)c * NTOT * BINS + (size_t)mBase * BINS;
    const __half* srcB = g_cbh + (size_t)c * Ee   * BINS + (size_t)eBase * BINS;

    const uint32_t sbase = (uint32_t)__cvta_generic_to_shared(S);

    auto load_slab = [&](int k0, int buf) {
#pragma unroll
        for (int i = 0; i < 8; i++) {
            int id  = t + 256 * i;
            int m   = id >> 10;
            int cid = id & 1023;
            int row = cid >> 3;
            int q   = cid & 7;
            const __half* src = (m == 0 ? srcA : srcB) + (size_t)row * BINS + k0 + q * 8;
            cp16(sbase + (uint32_t)(buf * BUFB + m * MATB + row * 128
                                    + ((q ^ (row & 7)) << 4)),
                 src);
        }
        asm volatile("cp.async.commit_group;");
    };

    float acc[4][4][4];
#pragma unroll
    for (int mi = 0; mi < 4; mi++)
#pragma unroll
        for (int ni = 0; ni < 4; ni++)
#pragma unroll
            for (int r = 0; r < 4; r++) acc[mi][ni][r] = 0.0f;

    load_slab(0, 0);
    if (t < BE) e2s[t] = g_e2[c * Ee + eBase + t];

    const int amat = lane >> 3;
    const int arow = lane & 7;
    const int a_row_off = ((amat & 1) << 3) + arow;
    const int a_ck_off  = amat >> 1;
    const int b_ck_off  = amat & 1;

    for (int s = 0; s < BINS / BKh; s++) {
        const int buf = s & 1;
        asm volatile("cp.async.wait_group 0;");
        __syncthreads();
        if (s + 1 < BINS / BKh) load_slab((s + 1) * BKh, buf ^ 1);

        const uint32_t Ah = sbase + buf * BUFB;
        const uint32_t Bh = Ah + MATB;

#pragma unroll
        for (int ks = 0; ks < BKh; ks += 16) {
            const int cks = ks >> 3;
            uint32_t aF[4][4], bF[4][2];
#pragma unroll
            for (int mi = 0; mi < 4; mi++) {
                int row = m_base + mi * 16 + a_row_off;
                int ch  = cks + a_ck_off;
                ldsm_x4(Ah + row * 128 + ((ch ^ (row & 7)) << 4),
                        aF[mi][0], aF[mi][1], aF[mi][2], aF[mi][3]);
            }
#pragma unroll
            for (int ni = 0; ni < 4; ni++) {
                int row = n_base + ni * 8 + arow;
                int ch  = cks + b_ck_off;
                ldsm_x2(Bh + row * 128 + ((ch ^ (row & 7)) << 4),
                        bF[ni][0], bF[ni][1]);
            }
#pragma unroll
            for (int mi = 0; mi < 4; mi++)
#pragma unroll
                for (int ni = 0; ni < 4; ni++)
                    MMA_F16(acc[mi][ni], aF[mi], bF[ni]);
        }
        __syncthreads();
    }

    // epilogue: write approx scores e2 - 2*dot as fp16 (half2 stores)
    const int r4 = lane >> 2;
    const int c4 = lane & 3;
#pragma unroll
    for (int mi = 0; mi < 4; mi++)
#pragma unroll
        for (int h = 0; h < 2; h++) {
            int grow = mBase + m_base + mi * 16 + r4 + h * 8;
            __half* dr = g_dh + ((size_t)c * NTOT + grow) * Ee + eBase;
#pragma unroll
            for (int ni = 0; ni < 4; ni++) {
                int cl = n_base + ni * 8 + c4 * 2;
                float sx = e2s[cl]     - 2.0f * acc[mi][ni][h * 2 + 0];
                float sy = e2s[cl + 1] - 2.0f * acc[mi][ni][h * 2 + 1];
                *(__half2*)(dr + cl) = __floats2half2_rn(sx, sy);
            }
        }
}

// ---------------- select: certified argmin, warp per row --------------------
#define CAND_CAP 128

__global__ __launch_bounds__(256) void select_k(const float* __restrict__ cb) {
    __shared__ int scand[8][CAND_CAP];
    __shared__ int scnt[8];

    const int t    = threadIdx.x;
    const int lane = t & 31;
    const int wp   = t >> 5;
    const int n    = blockIdx.x * 8 + wp;
    const int c    = blockIdx.y;
    const size_t row = (size_t)c * NTOT + n;

    const uint4* dr = (const uint4*)(g_dh + row * Ee);
    uint4 sc[4];
    float lmin = 3.4e38f;
#pragma unroll
    for (int j = 0; j < 4; j++) {
        sc[j] = dr[lane + 32 * j];
        const __half2* h2 = (const __half2*)&sc[j];
#pragma unroll
        for (int k = 0; k < 4; k++) {
            float2 f2 = __half22float2(h2[k]);
            lmin = fminf(lmin, fminf(f2.x, f2.y));
        }
    }
#pragma unroll
    for (int o = 16; o; o >>= 1)
        lmin = fminf(lmin, __shfl_xor_sync(0xffffffffu, lmin, o));

    const float sv = sqrtf(g_vn2[row]);
    const float se = sqrtf(__int_as_float(g_emax[c]));
    const float M  = (sv + se) * (sv + se);        // bound on |score|
    const float thr = lmin + 2.0f * (0.002f * sv * se + 0.1f) + 0.001f * M;

    int cntL = 0, idxL = 0x7fffffff;
#pragma unroll
    for (int j = 0; j < 4; j++) {
        const __half2* h2 = (const __half2*)&sc[j];
        int base = 8 * (lane + 32 * j);
#pragma unroll
        for (int k = 0; k < 4; k++) {
            float2 f2 = __half22float2(h2[k]);
            if (f2.x <= thr) { cntL++; idxL = min(idxL, base + 2 * k); }
            if (f2.y <= thr) { cntL++; idxL = min(idxL, base + 2 * k + 1); }
        }
    }
    int cnt = cntL, idxm = idxL;
#pragma unroll
    for (int o = 16; o; o >>= 1) {
        cnt  += __shfl_xor_sync(0xffffffffu, cnt, o);
        idxm  = min(idxm, __shfl_xor_sync(0xffffffffu, idxm, o));
    }

    if (cnt == 1) {            // sole candidate in certified window = argmin
        if (lane == 0) g_arg[row] = (unsigned long long)(unsigned)idxm;
        return;
    }

    if (lane == 0) scnt[wp] = 0;
    __syncwarp();
    bool full_scan = (cnt > CAND_CAP);
    if (!full_scan) {
#pragma unroll
        for (int j = 0; j < 4; j++) {
            const __half2* h2 = (const __half2*)&sc[j];
            int base = 8 * (lane + 32 * j);
#pragma unroll
            for (int k = 0; k < 4; k++) {
                float2 f2 = __half22float2(h2[k]);
                if (f2.x <= thr) scand[wp][atomicAdd(&scnt[wp], 1)] = base + 2 * k;
                if (f2.y <= thr) scand[wp][atomicAdd(&scnt[wp], 1)] = base + 2 * k + 1;
            }
        }
    }
    __syncwarp();

    const float4* vr = (const float4*)(g_v + row * BINS);
    float4 v[8];
#pragma unroll
    for (int j = 0; j < 8; j++) v[j] = vr[lane + 32 * j];

    float best = 3.4e38f;
    int   bidx = 0x7fffffff;
    const int total = full_scan ? Ee : cnt;
    for (int ci = 0; ci < total; ci++) {
        const int e = full_scan ? ci : scand[wp][ci];
        const float4* cr = (const float4*)(cb + ((size_t)c * Ee + e) * BINS);
        float p = 0.0f;
#pragma unroll
        for (int j = 0; j < 8; j++) {
            float4 cv = cr[lane + 32 * j];
            p += v[j].x * cv.x + v[j].y * cv.y + v[j].z * cv.z + v[j].w * cv.w;
        }
#pragma unroll
        for (int o = 16; o; o >>= 1)
            p += __shfl_xor_sync(0xffffffffu, p, o);
        float s = g_e2[c * Ee + e] - 2.0f * p;
        if (s < best || (s == best && e < bidx)) { best = s; bidx = e; }
    }
    if (lane == 0) g_arg[row] = (unsigned long long)(unsigned)bidx;
}

// ---------------- gather + transpose + channel-reverse + loss --------------
__global__ __launch_bounds__(256) void gather_k(const float* __restrict__ cb,
                                                float* __restrict__ out)
{
    __shared__ float qs[32][33];
    __shared__ int   idxs[32];
    __shared__ float rsum[256];

    const int t    = threadIdx.x;
    const int c    = blockIdx.z;
    const int n0   = blockIdx.y * 32;
    const int bin0 = blockIdx.x * 32;

    if (t < 32) idxs[t] = (int)(g_arg[c * NTOT + n0 + t] & 0xFFFFFFFFULL);
    __syncthreads();

    {
        int binL = t % 32, fL0 = t / 32;
        float lacc = 0.0f;
#pragma unroll
        for (int i = 0; i < 4; i++) {
            int fL = fL0 + 8 * i;
            int n  = n0 + fL;
            float qv = cb[((size_t)c * Ee + idxs[fL]) * BINS + bin0 + binL];
            float vv = g_v[((size_t)c * NTOT + n) * BINS + bin0 + binL];
            float d = qv - vv;
            lacc += d * d;
            qs[fL][binL] = qv;
        }
        rsum[t] = lacc;
    }
    __syncthreads();

    {
        int fL = t % 32, bL0 = t / 32;
        int b = n0 / FRAMES, fbase = n0 % FRAMES;
        int cOut = (Cc - 1) - c;
#pragma unroll
        for (int i = 0; i < 4; i++) {
            int bL = bL0 + 8 * i;
            out[(((size_t)b * Cc + cOut) * BINS + bin0 + bL) * FRAMES + fbase + fL]
                = qs[fL][bL];
        }
    }
    __syncthreads();
    for (int s2 = 128; s2; s2 >>= 1) {
        if (t < s2) rsum[t] += rsum[t + s2];
        __syncthreads();
    }
    if (t == 0) atomicAdd(&g_loss, rsum[0]);
}

// ---------------- finalize loss --------------------------------------------
__global__ void fin_k(float* __restrict__ out, int lossIdx) {
    if (threadIdx.x == 0)
        out[lossIdx] = 1.25f * g_loss / (float)((size_t)NTOT * BINS);
}

// ---------------- launch ----------------------------------------------------
extern "C" void kernel_launch(void* const* d_in, const int* in_sizes, int n_in,
                              void* d_out, int out_size)
{
    const float* x  = (const float*)d_in[0];
    const float* w1 = (const float*)d_in[1];
    const float* b1 = (const float*)d_in[2];
    const float* w2 = (const float*)d_in[3];
    const float* b2 = (const float*)d_in[4];
    const float* ws = (const float*)d_in[5];
    const float* bs = (const float*)d_in[6];
    const float* cb = (const float*)d_in[7];
    float* out = (float*)d_out;

    cudaFuncSetAttribute(gemm_k,
                         cudaFuncAttributeMaxDynamicSharedMemorySize,
                         GEMM_SMEM_BYTES);

    init_k<<<1, 256>>>();
    conv_k<<<dim3(BINS / BT, FRAMES / FT, Bq), 256>>>(x, w1, b1, w2, b2, ws, bs);
    e2_k<<<(Cc * Ee) / 8, 256>>>(cb);
    vn2_k<<<(Cc * NTOT) / 8, 256>>>();
    gemm_k<<<dim3(Ee / BE, NTOT / BM, Cc), 256, GEMM_SMEM_BYTES>>>();
    select_k<<<dim3(NTOT / 8, Cc), 256>>>(cb);
    gather_k<<<dim3(BINS / 32, NTOT / 32, Cc), 256>>>(cb, out);
    fin_k<<<1, 32>>>(out, out_size - 1);
}

// round 17
// speedup vs baseline: 1.5564x; 1.4124x over previous
#include <cuda_runtime.h>
#include <cuda_fp16.h>
#include <cstdint>

#define Bq      8
#define CIN     2
#define BINS    1024
#define FRAMES  512
#define Cc      8
#define Ee      1024
#define NTOT    (Bq * FRAMES)      // 4096 vectors per codebook channel

// ---------------- scratch (device globals: no allocation allowed) ----------
__device__ __align__(256) float  g_v [(size_t)Cc * NTOT * BINS]; // v[c][n][bin]
__device__ __align__(256) __half g_vh[(size_t)Cc * NTOT * BINS]; // fp16(v)
__device__ __align__(256) __half g_cbh[(size_t)Cc * Ee * BINS];  // fp16(cb)
__device__ __align__(256) __half g_dh[(size_t)Cc * NTOT * Ee];   // approx scores
__device__ __align__(256) float  g_e2[Cc * Ee];
__device__ __align__(256) float  g_vn2[Cc * NTOT];               // row norms^2
__device__ int   g_emax[Cc];                                     // max e2 bits
__device__ __align__(256) unsigned long long g_arg[Cc * NTOT];
__device__ float g_loss;

// ---------------- init ------------------------------------------------------
__global__ void init_k() {
    int i = blockIdx.x * blockDim.x + threadIdx.x;
    if (i == 0) g_loss = 0.0f;
    if (i < Cc) g_emax[i] = 0;
}

// ---------------- fused conv1 -> leaky -> conv2 + skip -> v (+fp16) --------
// BT=32 tiles: lower stage-2 halo overhead (1.25x vs 1.5x) and 4 frame
// positions per thread in stage 3 (weight LDS amortized 4x). Dynamic smem.
#define BT 32
#define FT 32
#define XROWS (BT + 16)   // 48
#define HROWS (BT + 8)    // 40
#define XS_F   (CIN * XROWS * (FT + 1))     // 3168
#define H1_F   (Cc * HROWS * (FT + 1))      // 10560
#define CONV_SMEM ((XS_F + H1_F + 144 + 576 + 16 + 24) * 4)   // 57952 B

__global__ __launch_bounds__(256) void conv_k(
    const float* __restrict__ x,
    const float* __restrict__ w1, const float* __restrict__ b1,
    const float* __restrict__ w2, const float* __restrict__ b2,
    const float* __restrict__ ws, const float* __restrict__ bs)
{
    extern __shared__ float SM[];
    float* xsf  = SM;                    // [CIN][48][33]
    float* h1f  = xsf + XS_F;            // [Cc][40][33]
    float* w1s  = h1f + H1_F;            // 144
    float* w2s  = w1s + 144;             // 576
    float* wss  = w2s + 576;             // 16
    float* b1sh = wss + 16;              // 8
    float* b2sh = b1sh + 8;              // 8
    float* bssh = b2sh + 8;              // 8

#define XS(ci, r, f)  xsf[((ci) * XROWS + (r)) * (FT + 1) + (f)]
#define H1(c, r, f)   h1f[((c) * HROWS + (r)) * (FT + 1) + (f)]

    const int t    = threadIdx.x;
    const int bin0 = blockIdx.x * BT;
    const int f0   = blockIdx.y * FT;
    const int b    = blockIdx.z;

    for (int i = t; i < Cc * CIN * 9; i += 256) w1s[i] = w1[i];
    for (int i = t; i < Cc * Cc * 9;  i += 256) w2s[i] = w2[i];
    if (t < Cc * CIN) wss[t] = ws[t];
    if (t < Cc) { b1sh[t] = b1[t]; b2sh[t] = b2[t]; bssh[t] = bs[t]; }

    // load x tile with halo 8
    for (int p = t; p < CIN * XROWS * FT; p += 256) {
        int f  = p % FT;
        int rb = (p / FT) % XROWS;
        int ci = p / (FT * XROWS);
        int gb = bin0 - 8 + rb;
        float v = 0.0f;
        if (gb >= 0 && gb < BINS)
            v = x[((size_t)(b * CIN + ci) * BINS + gb) * FRAMES + f0 + f];
        XS(ci, rb, f) = v;
    }
    __syncthreads();

    // stage 2: conv1 + leaky (h1 rows with halo 4)
    for (int p = t; p < HROWS * FT; p += 256) {
        int f  = p % FT;
        int rb = p / FT;
        int gb = bin0 - 4 + rb;
        float acc[Cc];
#pragma unroll
        for (int c = 0; c < Cc; c++) acc[c] = b1sh[c];
#pragma unroll
        for (int ci = 0; ci < CIN; ci++)
#pragma unroll
            for (int k = 0; k < 9; k++) {
                float xv = XS(ci, rb + k, f);
#pragma unroll
                for (int c = 0; c < Cc; c++)
                    acc[c] += xv * w1s[(c * CIN + ci) * 9 + k];
            }
#pragma unroll
        for (int c = 0; c < Cc; c++) {
            float h = acc[c];
            h = (h >= 0.0f) ? h : 0.2f * h;
            if (gb < 0 || gb >= BINS) h = 0.0f;
            H1(c, rb, f) = h;
        }
    }
    __syncthreads();

    // stage 3: conv2 + skip, 4 frame positions per thread
    const int binL = t % BT;      // 0..31
    const int fL0  = t / BT;      // 0..7
    float acc[4][Cc];
#pragma unroll
    for (int i = 0; i < 4; i++)
#pragma unroll
        for (int c = 0; c < Cc; c++) acc[i][c] = b2sh[c] + bssh[c];

#pragma unroll
    for (int c2 = 0; c2 < Cc; c2++)
#pragma unroll
        for (int k = 0; k < 9; k++) {
            float w[Cc];
#pragma unroll
            for (int c = 0; c < Cc; c++) w[c] = w2s[(c * Cc + c2) * 9 + k];
#pragma unroll
            for (int i = 0; i < 4; i++) {
                float hv = H1(c2, binL + k, fL0 + 8 * i);
#pragma unroll
                for (int c = 0; c < Cc; c++) acc[i][c] += hv * w[c];
            }
        }
#pragma unroll
    for (int ci = 0; ci < CIN; ci++)
#pragma unroll
        for (int i = 0; i < 4; i++) {
            float xv = XS(ci, binL + 8, fL0 + 8 * i);
#pragma unroll
            for (int c = 0; c < Cc; c++) acc[i][c] += xv * wss[c * CIN + ci];
        }

    const int gb = bin0 + binL;
#pragma unroll
    for (int i = 0; i < 4; i++) {
        int n = b * FRAMES + f0 + fL0 + 8 * i;
#pragma unroll
        for (int c = 0; c < Cc; c++) {
            size_t idx = ((size_t)c * NTOT + n) * BINS + gb;
            float vv = acc[i][c];
            g_v[idx]  = vv;
            g_vh[idx] = __float2half(vv);
        }
    }
#undef XS
#undef H1
}

// ---------------- e2 + fp16(cb) + per-channel max e2 ------------------------
__global__ void e2_k(const float* __restrict__ cb) {
    int warp = threadIdx.x >> 5, lane = threadIdx.x & 31;
    int row  = blockIdx.x * 8 + warp;              // 0..8191
    const size_t base = (size_t)row * BINS;
    float s = 0.0f;
    for (int j = lane; j < BINS; j += 32) {
        float v = cb[base + j];
        s += v * v;
        g_cbh[base + j] = __float2half(v);
    }
#pragma unroll
    for (int o = 16; o; o >>= 1) s += __shfl_down_sync(0xffffffffu, s, o);
    if (lane == 0) {
        g_e2[row] = s;
        atomicMax(&g_emax[row / Ee], __float_as_int(s));   // s >= 0
    }
}

// ---------------- vn2 ~= ||v row||^2 from fp16 (threshold-only) -------------
__global__ void vn2_k() {
    int warp = threadIdx.x >> 5, lane = threadIdx.x & 31;
    int row  = blockIdx.x * 8 + warp;              // 0..32767
    const uint4* p = (const uint4*)(g_vh + (size_t)row * BINS);
    float s = 0.0f;
#pragma unroll
    for (int j = 0; j < 4; j++) {
        uint4 u = p[lane + 32 * j];
        const __half2* h2 = (const __half2*)&u;
#pragma unroll
        for (int k = 0; k < 4; k++) {
            float2 f2 = __half22float2(h2[k]);
            s += f2.x * f2.x + f2.y * f2.y;
        }
    }
#pragma unroll
    for (int o = 16; o; o >>= 1) s += __shfl_down_sync(0xffffffffu, s, o);
    if (lane == 0) g_vn2[row] = s;
}

// ---------------- 1-pass fp16 tensor GEMM -> approx scores (fp16) -----------
#define BM   128
#define BE   128
#define BKh  64
#define MATB 16384
#define BUFB (2 * MATB)
#define GEMM_SMEM_BYTES (2 * BUFB)    // 65536

__device__ __forceinline__ void cp16(uint32_t dst, const void* src) {
    asm volatile("cp.async.cg.shared.global [%0], [%1], 16;" :: "r"(dst), "l"(src));
}

__device__ __forceinline__ void ldsm_x4(uint32_t a, uint32_t& r0, uint32_t& r1,
                                        uint32_t& r2, uint32_t& r3) {
    asm volatile("ldmatrix.sync.aligned.m8n8.x4.shared.b16 {%0,%1,%2,%3}, [%4];"
                 : "=r"(r0), "=r"(r1), "=r"(r2), "=r"(r3) : "r"(a));
}
__device__ __forceinline__ void ldsm_x2(uint32_t a, uint32_t& r0, uint32_t& r1) {
    asm volatile("ldmatrix.sync.aligned.m8n8.x2.shared.b16 {%0,%1}, [%2];"
                 : "=r"(r0), "=r"(r1) : "r"(a));
}

#define MMA_F16(d, a, b) \
    asm volatile("mma.sync.aligned.m16n8k16.row.col.f32.f16.f16.f32 " \
                 "{%0,%1,%2,%3}, {%4,%5,%6,%7}, {%8,%9}, {%0,%1,%2,%3};" \
                 : "+f"(d[0]), "+f"(d[1]), "+f"(d[2]), "+f"(d[3]) \
                 : "r"(a[0]), "r"(a[1]), "r"(a[2]), "r"(a[3]), \
                   "r"(b[0]), "r"(b[1]))

__global__ __launch_bounds__(256, 2) void gemm_k() {
    extern __shared__ __align__(128) char S[];
    __shared__ float e2s[BE];

    const int t    = threadIdx.x;
    const int lane = t & 31;
    const int w    = t >> 5;
    const int m_base = (w >> 2) * 64;
    const int n_base = (w & 3) * 32;

    const int c     = blockIdx.z;
    const int eBase = blockIdx.x * BE;
    const int mBase = blockIdx.y * BM;

    const __half* srcA = g_vh  + (size_t)c * NTOT * BINS + (size_t)mBase * BINS;
    const __half* srcB = g_cbh + (size_t)c * Ee   * BINS + (size_t)eBase * BINS;

    const uint32_t sbase = (uint32_t)__cvta_generic_to_shared(S);

    auto load_slab = [&](int k0, int buf) {
#pragma unroll
        for (int i = 0; i < 8; i++) {
            int id  = t + 256 * i;
            int m   = id >> 10;
            int cid = id & 1023;
            int row = cid >> 3;
            int q   = cid & 7;
            const __half* src = (m == 0 ? srcA : srcB) + (size_t)row * BINS + k0 + q * 8;
            cp16(sbase + (uint32_t)(buf * BUFB + m * MATB + row * 128
                                    + ((q ^ (row & 7)) << 4)),
                 src);
        }
        asm volatile("cp.async.commit_group;");
    };

    float acc[4][4][4];
#pragma unroll
    for (int mi = 0; mi < 4; mi++)
#pragma unroll
        for (int ni = 0; ni < 4; ni++)
#pragma unroll
            for (int r = 0; r < 4; r++) acc[mi][ni][r] = 0.0f;

    load_slab(0, 0);
    if (t < BE) e2s[t] = g_e2[c * Ee + eBase + t];

    const int amat = lane >> 3;
    const int arow = lane & 7;
    const int a_row_off = ((amat & 1) << 3) + arow;
    const int a_ck_off  = amat >> 1;
    const int b_ck_off  = amat & 1;

    for (int s = 0; s < BINS / BKh; s++) {
        const int buf = s & 1;
        asm volatile("cp.async.wait_group 0;");
        __syncthreads();
        if (s + 1 < BINS / BKh) load_slab((s + 1) * BKh, buf ^ 1);

        const uint32_t Ah = sbase + buf * BUFB;
        const uint32_t Bh = Ah + MATB;

#pragma unroll
        for (int ks = 0; ks < BKh; ks += 16) {
            const int cks = ks >> 3;
            uint32_t aF[4][4], bF[4][2];
#pragma unroll
            for (int mi = 0; mi < 4; mi++) {
                int row = m_base + mi * 16 + a_row_off;
                int ch  = cks + a_ck_off;
                ldsm_x4(Ah + row * 128 + ((ch ^ (row & 7)) << 4),
                        aF[mi][0], aF[mi][1], aF[mi][2], aF[mi][3]);
            }
#pragma unroll
            for (int ni = 0; ni < 4; ni++) {
                int row = n_base + ni * 8 + arow;
                int ch  = cks + b_ck_off;
                ldsm_x2(Bh + row * 128 + ((ch ^ (row & 7)) << 4),
                        bF[ni][0], bF[ni][1]);
            }
#pragma unroll
            for (int mi = 0; mi < 4; mi++)
#pragma unroll
                for (int ni = 0; ni < 4; ni++)
                    MMA_F16(acc[mi][ni], aF[mi], bF[ni]);
        }
        __syncthreads();
    }

    // epilogue: write approx scores e2 - 2*dot as fp16 (half2 stores)
    const int r4 = lane >> 2;
    const int c4 = lane & 3;
#pragma unroll
    for (int mi = 0; mi < 4; mi++)
#pragma unroll
        for (int h = 0; h < 2; h++) {
            int grow = mBase + m_base + mi * 16 + r4 + h * 8;
            __half* dr = g_dh + ((size_t)c * NTOT + grow) * Ee + eBase;
#pragma unroll
            for (int ni = 0; ni < 4; ni++) {
                int cl = n_base + ni * 8 + c4 * 2;
                float sx = e2s[cl]     - 2.0f * acc[mi][ni][h * 2 + 0];
                float sy = e2s[cl + 1] - 2.0f * acc[mi][ni][h * 2 + 1];
                *(__half2*)(dr + cl) = __floats2half2_rn(sx, sy);
            }
        }
}

// ---------------- select: certified argmin, warp per row --------------------
#define CAND_CAP 128

__global__ __launch_bounds__(256) void select_k(const float* __restrict__ cb) {
    __shared__ int scand[8][CAND_CAP];
    __shared__ int scnt[8];

    const int t    = threadIdx.x;
    const int lane = t & 31;
    const int wp   = t >> 5;
    const int n    = blockIdx.x * 8 + wp;
    const int c    = blockIdx.y;
    const size_t row = (size_t)c * NTOT + n;

    const uint4* dr = (const uint4*)(g_dh + row * Ee);
    uint4 sc[4];
    float lmin = 3.4e38f;
#pragma unroll
    for (int j = 0; j < 4; j++) {
        sc[j] = dr[lane + 32 * j];
        const __half2* h2 = (const __half2*)&sc[j];
#pragma unroll
        for (int k = 0; k < 4; k++) {
            float2 f2 = __half22float2(h2[k]);
            lmin = fminf(lmin, fminf(f2.x, f2.y));
        }
    }
#pragma unroll
    for (int o = 16; o; o >>= 1)
        lmin = fminf(lmin, __shfl_xor_sync(0xffffffffu, lmin, o));

    const float sv = sqrtf(g_vn2[row]);
    const float se = sqrtf(__int_as_float(g_emax[c]));
    const float M  = (sv + se) * (sv + se);        // bound on |score|
    const float thr = lmin + 2.0f * (0.002f * sv * se + 0.1f) + 0.001f * M;

    int cntL = 0, idxL = 0x7fffffff;
#pragma unroll
    for (int j = 0; j < 4; j++) {
        const __half2* h2 = (const __half2*)&sc[j];
        int base = 8 * (lane + 32 * j);
#pragma unroll
        for (int k = 0; k < 4; k++) {
            float2 f2 = __half22float2(h2[k]);
            if (f2.x <= thr) { cntL++; idxL = min(idxL, base + 2 * k); }
            if (f2.y <= thr) { cntL++; idxL = min(idxL, base + 2 * k + 1); }
        }
    }
    int cnt = cntL, idxm = idxL;
#pragma unroll
    for (int o = 16; o; o >>= 1) {
        cnt  += __shfl_xor_sync(0xffffffffu, cnt, o);
        idxm  = min(idxm, __shfl_xor_sync(0xffffffffu, idxm, o));
    }

    if (cnt == 1) {            // sole candidate in certified window = argmin
        if (lane == 0) g_arg[row] = (unsigned long long)(unsigned)idxm;
        return;
    }

    if (lane == 0) scnt[wp] = 0;
    __syncwarp();
    bool full_scan = (cnt > CAND_CAP);
    if (!full_scan) {
#pragma unroll
        for (int j = 0; j < 4; j++) {
            const __half2* h2 = (const __half2*)&sc[j];
            int base = 8 * (lane + 32 * j);
#pragma unroll
            for (int k = 0; k < 4; k++) {
                float2 f2 = __half22float2(h2[k]);
                if (f2.x <= thr) scand[wp][atomicAdd(&scnt[wp], 1)] = base + 2 * k;
                if (f2.y <= thr) scand[wp][atomicAdd(&scnt[wp], 1)] = base + 2 * k + 1;
            }
        }
    }
    __syncwarp();

    const float4* vr = (const float4*)(g_v + row * BINS);
    float4 v[8];
#pragma unroll
    for (int j = 0; j < 8; j++) v[j] = vr[lane + 32 * j];

    float best = 3.4e38f;
    int   bidx = 0x7fffffff;
    const int total = full_scan ? Ee : cnt;
    for (int ci = 0; ci < total; ci++) {
        const int e = full_scan ? ci : scand[wp][ci];
        const float4* cr = (const float4*)(cb + ((size_t)c * Ee + e) * BINS);
        float p = 0.0f;
#pragma unroll
        for (int j = 0; j < 8; j++) {
            float4 cv = cr[lane + 32 * j];
            p += v[j].x * cv.x + v[j].y * cv.y + v[j].z * cv.z + v[j].w * cv.w;
        }
#pragma unroll
        for (int o = 16; o; o >>= 1)
            p += __shfl_xor_sync(0xffffffffu, p, o);
        float s = g_e2[c * Ee + e] - 2.0f * p;
        if (s < best || (s == best && e < bidx)) { best = s; bidx = e; }
    }
    if (lane == 0) g_arg[row] = (unsigned long long)(unsigned)bidx;
}

// ---------------- gather + transpose + channel-reverse + loss --------------
__global__ __launch_bounds__(256) void gather_k(const float* __restrict__ cb,
                                                float* __restrict__ out)
{
    __shared__ float qs[32][33];
    __shared__ int   idxs[32];
    __shared__ float rsum[256];

    const int t    = threadIdx.x;
    const int c    = blockIdx.z;
    const int n0   = blockIdx.y * 32;
    const int bin0 = blockIdx.x * 32;

    if (t < 32) idxs[t] = (int)(g_arg[c * NTOT + n0 + t] & 0xFFFFFFFFULL);
    __syncthreads();

    {
        int binL = t % 32, fL0 = t / 32;
        float lacc = 0.0f;
#pragma unroll
        for (int i = 0; i < 4; i++) {
            int fL = fL0 + 8 * i;
            int n  = n0 + fL;
            float qv = cb[((size_t)c * Ee + idxs[fL]) * BINS + bin0 + binL];
            float vv = g_v[((size_t)c * NTOT + n) * BINS + bin0 + binL];
            float d = qv - vv;
            lacc += d * d;
            qs[fL][binL] = qv;
        }
        rsum[t] = lacc;
    }
    __syncthreads();

    {
        int fL = t % 32, bL0 = t / 32;
        int b = n0 / FRAMES, fbase = n0 % FRAMES;
        int cOut = (Cc - 1) - c;
#pragma unroll
        for (int i = 0; i < 4; i++) {
            int bL = bL0 + 8 * i;
            out[(((size_t)b * Cc + cOut) * BINS + bin0 + bL) * FRAMES + fbase + fL]
                = qs[fL][bL];
        }
    }
    __syncthreads();
    for (int s2 = 128; s2; s2 >>= 1) {
        if (t < s2) rsum[t] += rsum[t + s2];
        __syncthreads();
    }
    if (t == 0) atomicAdd(&g_loss, rsum[0]);
}

// ---------------- finalize loss --------------------------------------------
__global__ void fin_k(float* __restrict__ out, int lossIdx) {
    if (threadIdx.x == 0)
        out[lossIdx] = 1.25f * g_loss / (float)((size_t)NTOT * BINS);
}

// ---------------- launch ----------------------------------------------------
extern "C" void kernel_launch(void* const* d_in, const int* in_sizes, int n_in,
                              void* d_out, int out_size)
{
    const float* x  = (const float*)d_in[0];
    const float* w1 = (const float*)d_in[1];
    const float* b1 = (const float*)d_in[2];
    const float* w2 = (const float*)d_in[3];
    const float* b2 = (const float*)d_in[4];
    const float* ws = (const float*)d_in[5];
    const float* bs = (const float*)d_in[6];
    const float* cb = (const float*)d_in[7];
    float* out = (float*)d_out;

    cudaFuncSetAttribute(gemm_k,
                         cudaFuncAttributeMaxDynamicSharedMemorySize,
                         GEMM_SMEM_BYTES);
    cudaFuncSetAttribute(conv_k,
                         cudaFuncAttributeMaxDynamicSharedMemorySize,
                         CONV_SMEM);

    init_k<<<1, 256>>>();
    conv_k<<<dim3(BINS / BT, FRAMES / FT, Bq), 256, CONV_SMEM>>>(
        x, w1, b1, w2, b2, ws, bs);
    e2_k<<<(Cc * Ee) / 8, 256>>>(cb);
    vn2_k<<<(Cc * NTOT) / 8, 256>>>();
    gemm_k<<<dim3(Ee / BE, NTOT / BM, Cc), 256, GEMM_SMEM_BYTES>>>();
    select_k<<<dim3(NTOT / 8, Cc), 256>>>(cb);
    gather_k<<<dim3(BINS / 32, NTOT / 32, Cc), 256>>>(cb, out);
    fin_k<<<1, 32>>>(out, out_size - 1);
}